// round 7
// baseline (speedup 1.0000x reference)
#include <cuda_runtime.h>
#include <cuda_bf16.h>

// Weighted BCE mean reduction, single fused kernel.
// loss_i = y_i==1 ? -log(x_i)*w1 : -log(1-x_i)*w0 ; out = mean(loss)
// N = 33554432. HBM-bound: 256 MB mandatory read; ~6.1 TB/s measured ceiling.
// R7: champion structure + 256-bit loads (ld.global.nc.v8, sm_100+) ->
//     1024B/warp request granularity, half the LDG count per stream.

#define RBLOCKS 1184          // 148 SMs * 8 resident blocks (one full wave)
#define RTHREADS 256
#define LN2F 0.6931471805599453f

__device__ float g_partials[RBLOCKS];
__device__ unsigned int g_count;   // zero-init; reset by last block each replay

__device__ __forceinline__ void ldg256_f32(const float* p, float* v) {
    asm volatile("ld.global.nc.v8.f32 {%0,%1,%2,%3,%4,%5,%6,%7}, [%8];"
                 : "=f"(v[0]), "=f"(v[1]), "=f"(v[2]), "=f"(v[3]),
                   "=f"(v[4]), "=f"(v[5]), "=f"(v[6]), "=f"(v[7])
                 : "l"(p));
}

__device__ __forceinline__ void ldg256_s32(const int* p, int* v) {
    asm volatile("ld.global.nc.v8.b32 {%0,%1,%2,%3,%4,%5,%6,%7}, [%8];"
                 : "=r"(v[0]), "=r"(v[1]), "=r"(v[2]), "=r"(v[3]),
                   "=r"(v[4]), "=r"(v[5]), "=r"(v[6]), "=r"(v[7])
                 : "l"(p));
}

__global__ __launch_bounds__(RTHREADS, 8)
void wbce_kernel(const float* __restrict__ x,
                 const int* __restrict__ y,
                 const float* __restrict__ w,
                 int n8, float inv_n,
                 float* __restrict__ out)
{
    // fold -ln2 into the weights: -log(t)*w == log2(t) * (-w*ln2)
    const float lw0 = -__ldg(&w[0]) * LN2F;
    const float lw1 = -__ldg(&w[1]) * LN2F;

    float acc0 = 0.0f, acc1 = 0.0f;
    const int stride = gridDim.x * blockDim.x;     // in units of 8 elements
    int i = blockIdx.x * blockDim.x + threadIdx.x;

    // unroll x2: four 256-bit loads issued back-to-back before dependent math
    for (; i + stride < n8; i += 2 * stride) {
        float xa[8], xb[8];
        int   ya[8], yb[8];
        ldg256_f32(x + (size_t)i * 8, xa);
        ldg256_s32(y + (size_t)i * 8, ya);
        ldg256_f32(x + (size_t)(i + stride) * 8, xb);
        ldg256_s32(y + (size_t)(i + stride) * 8, yb);

        #pragma unroll
        for (int j = 0; j < 8; j += 2) {
            float ta = (ya[j]     == 1) ? xa[j]     : (1.0f - xa[j]);
            float tb = (ya[j + 1] == 1) ? xa[j + 1] : (1.0f - xa[j + 1]);
            float ua = (ya[j]     == 1) ? lw1 : lw0;
            float ub = (ya[j + 1] == 1) ? lw1 : lw0;
            acc0 = fmaf(__log2f(ta), ua, acc0);
            acc1 = fmaf(__log2f(tb), ub, acc1);
        }
        #pragma unroll
        for (int j = 0; j < 8; j += 2) {
            float ta = (yb[j]     == 1) ? xb[j]     : (1.0f - xb[j]);
            float tb = (yb[j + 1] == 1) ? xb[j + 1] : (1.0f - xb[j + 1]);
            float ua = (yb[j]     == 1) ? lw1 : lw0;
            float ub = (yb[j + 1] == 1) ? lw1 : lw0;
            acc0 = fmaf(__log2f(ta), ua, acc0);
            acc1 = fmaf(__log2f(tb), ub, acc1);
        }
    }
    // tail (at most one strided 8-group per thread)
    for (; i < n8; i += stride) {
        float xv[8];
        int   yv[8];
        ldg256_f32(x + (size_t)i * 8, xv);
        ldg256_s32(y + (size_t)i * 8, yv);
        #pragma unroll
        for (int j = 0; j < 8; j += 2) {
            float ta = (yv[j]     == 1) ? xv[j]     : (1.0f - xv[j]);
            float tb = (yv[j + 1] == 1) ? xv[j + 1] : (1.0f - xv[j + 1]);
            float ua = (yv[j]     == 1) ? lw1 : lw0;
            float ub = (yv[j + 1] == 1) ? lw1 : lw0;
            acc0 = fmaf(__log2f(ta), ua, acc0);
            acc1 = fmaf(__log2f(tb), ub, acc1);
        }
    }

    float acc = acc0 + acc1;

    // intra-block reduce
    #pragma unroll
    for (int off = 16; off > 0; off >>= 1)
        acc += __shfl_xor_sync(0xFFFFFFFFu, acc, off);

    __shared__ float warp_sums[RTHREADS / 32];
    __shared__ bool s_is_last;
    int lane = threadIdx.x & 31;
    int wid  = threadIdx.x >> 5;
    if (lane == 0) warp_sums[wid] = acc;
    __syncthreads();

    if (wid == 0) {
        float v = (lane < RTHREADS / 32) ? warp_sums[lane] : 0.0f;
        #pragma unroll
        for (int off = 16; off > 0; off >>= 1)
            v += __shfl_xor_sync(0xFFFFFFFFu, v, off);
        if (lane == 0) {
            g_partials[blockIdx.x] = v;
            __threadfence();
            unsigned int t = atomicAdd(&g_count, 1u);
            s_is_last = (t == gridDim.x - 1);
        }
    }
    __syncthreads();

    // last block folds all partials -> out
    if (s_is_last) {
        volatile float* parts = g_partials;
        float a = 0.0f;
        for (int j = threadIdx.x; j < RBLOCKS; j += RTHREADS)
            a += parts[j];

        #pragma unroll
        for (int off = 16; off > 0; off >>= 1)
            a += __shfl_xor_sync(0xFFFFFFFFu, a, off);

        if (lane == 0) warp_sums[wid] = a;
        __syncthreads();

        if (wid == 0) {
            float v = (lane < RTHREADS / 32) ? warp_sums[lane] : 0.0f;
            #pragma unroll
            for (int off = 16; off > 0; off >>= 1)
                v += __shfl_xor_sync(0xFFFFFFFFu, v, off);
            if (lane == 0) {
                out[0] = v * inv_n;
                g_count = 0;          // reset for next graph replay
            }
        }
    }
}

extern "C" void kernel_launch(void* const* d_in, const int* in_sizes, int n_in,
                              void* d_out, int out_size)
{
    const float* x = (const float*)d_in[0];
    const int*   y = (const int*)d_in[1];
    const float* w = (const float*)d_in[2];
    float* out = (float*)d_out;

    int n  = in_sizes[0];
    int n8 = n / 8;

    wbce_kernel<<<RBLOCKS, RTHREADS>>>(x, y, w, n8, 1.0f / (float)n, out);
}